// round 6
// baseline (speedup 1.0000x reference)
#include <cuda_runtime.h>
#include <cuda_fp16.h>
#include <cstdint>
#include <cstddef>

#define TB    32
#define C_    256
#define NSP   3136
#define HEADS 8
#define DH    32
#define O_FACTOR 0.044194173824159216f

// ---------------- static scratch ----------------
__device__ unsigned char g_q[(size_t)TB * C_ * NSP];
__device__ unsigned char g_k[(size_t)TB * C_ * NSP];
__device__ unsigned char g_v[(size_t)TB * C_ * NSP];
__device__ __half g_obf[(size_t)TB * NSP * C_];   // [tb][n][c] o ints 0..8
__device__ __half g_wA[2 * 768 * 256];            // qkv weights, 2-way fp16 split
__device__ __half g_wP[2 * 256 * 256];            // proj weights (x1/8), 2-way fp16 split
__device__ int g_kvi[TB * HEADS * DH * DH];       // exact integer kv accumulators

// ---------------- helpers ----------------
__device__ __forceinline__ float quant8(float x) {
    return fminf(fmaxf(rintf(x), 0.0f), 8.0f);
}
__device__ __forceinline__ uint32_t smem_u32(const void* p) {
    uint32_t a;
    asm("{ .reg .u64 t; cvta.to.shared.u64 t, %1; cvt.u32.u64 %0, t; }" : "=r"(a) : "l"(p));
    return a;
}
#define SWZ(x) ((x) ^ (((x) >> 3) & 0x70))

__device__ __forceinline__ void cp16(uint32_t s, const void* g, uint32_t nbytes) {
    asm volatile("cp.async.cg.shared.global [%0], [%1], 16, %2;"
                 :: "r"(s), "l"(g), "r"(nbytes) : "memory");
}
#define CP_COMMIT() asm volatile("cp.async.commit_group;" ::: "memory")
#define CP_WAIT1()  asm volatile("cp.async.wait_group 1;" ::: "memory")
#define CP_WAIT0()  asm volatile("cp.async.wait_group 0;" ::: "memory")

#define LDSM_X4(r0, r1, r2, r3, addr) \
    asm volatile("ldmatrix.sync.aligned.m8n8.x4.shared.b16 {%0,%1,%2,%3}, [%4];" \
                 : "=r"(r0), "=r"(r1), "=r"(r2), "=r"(r3) : "r"(addr))

#define MMA16816(c, a, b) \
    asm volatile("mma.sync.aligned.m16n8k16.row.col.f32.f16.f16.f32 " \
                 "{%0,%1,%2,%3}, {%4,%5,%6,%7}, {%8,%9}, {%0,%1,%2,%3};" \
                 : "+f"((c)[0]), "+f"((c)[1]), "+f"((c)[2]), "+f"((c)[3]) \
                 : "r"((a)[0]), "r"((a)[1]), "r"((a)[2]), "r"((a)[3]), \
                   "r"((b)[0]), "r"((b)[1]))

// ---------------------------------------------------------------------------
// Kernel 0: exact 2-way fp16 split of weights + zero the kv int accumulators.
// ---------------------------------------------------------------------------
__global__ void split_weights(const float* __restrict__ qw, const float* __restrict__ kw,
                              const float* __restrict__ vw, const float* __restrict__ pw) {
    int idx = blockIdx.x * 256 + threadIdx.x;  // 0..262143
    g_kvi[idx] = 0;                            // 262144 == TB*HEADS*DH*DH
    float w;
    __half* dst;
    int stride;
    if (idx < 196608) {
        int row = idx >> 8, col = idx & 255;
        w = (row < 256) ? qw[row * 256 + col]
          : (row < 512) ? kw[(row - 256) * 256 + col]
                        : vw[(row - 512) * 256 + col];
        dst = g_wA + idx; stride = 196608;
    } else {
        int i2 = idx - 196608;
        w = pw[i2] * 0.125f;
        dst = g_wP + i2; stride = 65536;
    }
    __half h1 = __float2half_rn(w);
    float f1 = __half2float(h1);
    __half h2 = __float2half_rn(w - f1);
    dst[0] = h1; dst[stride] = h2;
}

// ---------------------------------------------------------------------------
// Kernel 1: HMMA GEMM, one CTA per (n-block, tb), m-looped with resident B.
// mode 0: B built from x (quant+transpose in-CTA), 6 m-tiles -> q/k/v uint8.
// mode 1: B cp.async from g_obf, 2 m-tiles -> BN -> fp32 out.
// A (weight splits) streamed double-buffered continuously across all chunks.
// ---------------------------------------------------------------------------
__global__ void __launch_bounds__(256, 2)
mma_gemm(int mode, const float* __restrict__ x,
         const float* __restrict__ bnA, const float* __restrict__ bnB,
         const float* __restrict__ bnC, float* __restrict__ outf) {
    extern __shared__ char smraw[];
    const uint32_t sbase = (smem_u32(smraw) + 1023u) & ~1023u;
    char* sm = smraw + (sbase - smem_u32(smraw));
    const uint32_t B_OFF = 0, A_OFF = 65536;   // B: 4 kc-blocks x 16KB; A: 2 bufs x 16KB

    const int tid = threadIdx.x;
    const int lane = tid & 31;
    const int wid = tid >> 5;
    const int wm = wid >> 1;
    const int wn = wid & 1;
    const int n0 = blockIdx.x << 7;
    const int tb = blockIdx.y;

    const __half* wsplit = mode ? g_wP : g_wA;
    const int wrows = mode ? 256 : 768;
    const int NG = mode ? 16 : 48;             // total A chunks (m-tiles x 8)

    const int ks8 = tid & 7;
    const int rbase = tid >> 3;

    auto load_chunkA = [&](int g, int buf) {
        int s = (g >> 2) & 1, kc = g & 3, mi = g >> 3;
        const __half* abase = wsplit + ((size_t)(s * wrows + mi * 128)) * 256 + kc * 64;
#pragma unroll
        for (int it = 0; it < 4; it++) {
            int row = it * 32 + rbase;
            uint32_t sa = sbase + A_OFF + buf * 16384 + SWZ(row * 128 + ks8 * 16);
            cp16(sa, abase + (size_t)row * 256 + ks8 * 8, 16);
        }
    };

    // ---- B fill ----
    if (mode == 0) {
        // from x [tb][c][n] fp32: quant -> fp16, transpose to K-major rows (n).
        const float* xb = x + (size_t)tb * C_ * NSP;
        int c = tid >> 5;
        int nn = (lane) * 4;
        int gn = n0 + nn;
#pragma unroll 4
        for (int pass = 0; pass < 32; pass++, c += 8) {
            float4 xv = make_float4(0.f, 0.f, 0.f, 0.f);
            if (gn + 3 < NSP) {
                xv = *reinterpret_cast<const float4*>(xb + (size_t)c * NSP + gn);
            } else if (gn < NSP) {
                const float* p = xb + (size_t)c * NSP;
                xv.x = p[gn];
                if (gn + 1 < NSP) xv.y = p[gn + 1];
                if (gn + 2 < NSP) xv.z = p[gn + 2];
            }
            __half h0 = __float2half_rn(quant8(xv.x) * 0.125f);
            __half h1 = __float2half_rn(quant8(xv.y) * 0.125f);
            __half h2 = __float2half_rn(quant8(xv.z) * 0.125f);
            __half h3 = __float2half_rn(quant8(xv.w) * 0.125f);
            int blk = c >> 6, col = (c & 63) * 2;
            char* bb = sm + B_OFF + blk * 16384;
            *reinterpret_cast<__half*>(bb + SWZ((nn + 0) * 128 + col)) = h0;
            *reinterpret_cast<__half*>(bb + SWZ((nn + 1) * 128 + col)) = h1;
            *reinterpret_cast<__half*>(bb + SWZ((nn + 2) * 128 + col)) = h2;
            *reinterpret_cast<__half*>(bb + SWZ((nn + 3) * 128 + col)) = h3;
        }
    } else {
        const __half* bsrc = g_obf + (size_t)tb * NSP * C_;
#pragma unroll
        for (int it = 0; it < 16; it++) {
            int seg = it * 256 + tid;
            int blk = seg >> 10;
            int within = seg & 1023;
            int row = within >> 3;
            int k8 = within & 7;
            int gn = n0 + row;
            uint32_t ok = (gn < NSP) ? 16u : 0u;
            uint32_t sa = sbase + B_OFF + blk * 16384 + SWZ(row * 128 + k8 * 16);
            cp16(sa, bsrc + (size_t)gn * 256 + blk * 64 + k8 * 8, ok);
        }
    }
    load_chunkA(0, 0);
    CP_COMMIT();          // group 0: (B if mode1) + A0
    load_chunkA(1, 1);
    CP_COMMIT();          // group 1: A1

    float acc[2][8][4];
#pragma unroll
    for (int i = 0; i < 2; i++)
#pragma unroll
        for (int j = 0; j < 8; j++)
#pragma unroll
            for (int l = 0; l < 4; l++) acc[i][j][l] = 0.0f;

#pragma unroll 1
    for (int g = 0; g < NG; g++) {
        if (g + 1 < NG) CP_WAIT1(); else CP_WAIT0();
        __syncthreads();

        uint32_t Ab = sbase + A_OFF + (g & 1) * 16384;
        uint32_t Bb = sbase + B_OFF + (g & 3) * 16384;
#pragma unroll
        for (int ks = 0; ks < 4; ks++) {
            uint32_t a[2][4], b[8][2];
#pragma unroll
            for (int tm = 0; tm < 2; tm++) {
                int row = wm * 32 + tm * 16 + (lane & 15);
                uint32_t ad = Ab + SWZ(row * 128 + ks * 32 + (lane >> 4) * 16);
                LDSM_X4(a[tm][0], a[tm][1], a[tm][2], a[tm][3], ad);
            }
#pragma unroll
            for (int tp = 0; tp < 4; tp++) {
                int row = wn * 64 + tp * 16 + (lane & 15);
                uint32_t bd = Bb + SWZ(row * 128 + ks * 32 + (lane >> 4) * 16);
                uint32_t r0, r1, r2, r3;
                LDSM_X4(r0, r1, r2, r3, bd);
                b[2 * tp][0] = r0; b[2 * tp][1] = r2;
                b[2 * tp + 1][0] = r1; b[2 * tp + 1][1] = r3;
            }
#pragma unroll
            for (int tm = 0; tm < 2; tm++)
#pragma unroll
                for (int tn = 0; tn < 8; tn++)
                    MMA16816(acc[tm][tn], a[tm], b[tn]);
        }
        __syncthreads();
        if (g + 2 < NG) { load_chunkA(g + 2, g & 1); CP_COMMIT(); }

        if ((g & 7) == 7) {
            // ---- epilogue for m-tile mi = g>>3 ----
            int mi = g >> 3;
#pragma unroll
            for (int tm = 0; tm < 2; tm++) {
#pragma unroll
                for (int h = 0; h < 2; h++) {
                    int gm = mi * 128 + wm * 32 + tm * 16 + (lane >> 2) + h * 8;
                    const float* bn;
                    unsigned char* out8 = nullptr;
                    int ch;
                    if (mode == 0) {
                        int mat = gm >> 8;
                        bn = (mat == 0) ? bnA : (mat == 1) ? bnB : bnC;
                        out8 = (mat == 0) ? g_q : (mat == 1) ? g_k : g_v;
                        ch = gm & 255;
                    } else {
                        bn = bnA;
                        ch = gm;
                    }
                    float s_ = bn[ch] / sqrtf(bn[768 + ch] + 1e-5f);
                    float t_ = __fsub_rn(bn[256 + ch], __fmul_rn(bn[512 + ch], s_));
                    size_t base = ((size_t)(tb * C_) + ch) * NSP;
#pragma unroll
                    for (int tn = 0; tn < 8; tn++) {
                        int n = n0 + wn * 64 + tn * 8 + (lane & 3) * 2;
                        if (n < NSP) {
                            float v0 = __fadd_rn(__fmul_rn(acc[tm][tn][2 * h + 0], s_), t_);
                            float v1 = __fadd_rn(__fmul_rn(acc[tm][tn][2 * h + 1], s_), t_);
                            if (mode == 0) {
                                uchar2 u;
                                u.x = (unsigned char)quant8(v0);
                                u.y = (unsigned char)quant8(v1);
                                *reinterpret_cast<uchar2*>(out8 + base + n) = u;
                            } else {
                                *reinterpret_cast<float2*>(outf + base + n) = make_float2(v0, v1);
                            }
                        }
                    }
                }
            }
#pragma unroll
            for (int i = 0; i < 2; i++)
#pragma unroll
                for (int j = 0; j < 8; j++)
#pragma unroll
                    for (int l = 0; l < 4; l++) acc[i][j][l] = 0.0f;
        }
    }
}

// ---------------------------------------------------------------------------
// Kernel 2: kv partial sums via dp4a over 64-n tiles, broadcast LDS.128 for k,
// conflict-free 32b LDS for v. atomicAdd(int) into g_kvi (exact).
// ---------------------------------------------------------------------------
__global__ void __launch_bounds__(256)
kv_kernel() {
    int tbh = blockIdx.y;
    int tb = tbh >> 3, h = tbh & 7;
    int nstart = blockIdx.x * 448;               // 7 chunks x 448 = 3136
    const unsigned char* kp = g_k + ((size_t)(tb * C_) + h * DH) * NSP + nstart;
    const unsigned char* vp = g_v + ((size_t)(tb * C_) + h * DH) * NSP + nstart;

    __shared__ uint32_t ks[32][20];   // 16 words used; stride 20 (16B-aligned rows)
    __shared__ uint32_t vs[32][17];   // stride 17 -> conflict-free 32b reads

    int tid = threadIdx.x;
    int fr = tid >> 3, fw = tid & 7;     // k fill: uint2 per thread
    int vr = tid >> 4, vw = tid & 15;    // v fill: 2 words per thread
    int d0 = (tid >> 5) * 4, e = tid & 31;
    int acc0 = 0, acc1 = 0, acc2 = 0, acc3 = 0;

#pragma unroll 1
    for (int it = 0; it < 7; it++) {
        int nn = it * 64;
        __syncthreads();
        uint2 kk = *reinterpret_cast<const uint2*>(kp + (size_t)fr * NSP + nn + fw * 8);
        ks[fr][fw * 2] = kk.x; ks[fr][fw * 2 + 1] = kk.y;
        vs[vr][vw]      = *reinterpret_cast<const uint32_t*>(vp + (size_t)vr * NSP + nn + vw * 4);
        vs[vr + 16][vw] = *reinterpret_cast<const uint32_t*>(vp + (size_t)(vr + 16) * NSP + nn + vw * 4);
        __syncthreads();
#pragma unroll
        for (int q = 0; q < 4; q++) {
            uint4 k0 = *reinterpret_cast<const uint4*>(&ks[d0 + 0][q * 4]);
            uint4 k1 = *reinterpret_cast<const uint4*>(&ks[d0 + 1][q * 4]);
            uint4 k2 = *reinterpret_cast<const uint4*>(&ks[d0 + 2][q * 4]);
            uint4 k3 = *reinterpret_cast<const uint4*>(&ks[d0 + 3][q * 4]);
            int v0 = (int)vs[e][q * 4 + 0];
            int v1 = (int)vs[e][q * 4 + 1];
            int v2 = (int)vs[e][q * 4 + 2];
            int v3 = (int)vs[e][q * 4 + 3];
            acc0 = __dp4a((int)k0.x, v0, acc0); acc0 = __dp4a((int)k0.y, v1, acc0);
            acc0 = __dp4a((int)k0.z, v2, acc0); acc0 = __dp4a((int)k0.w, v3, acc0);
            acc1 = __dp4a((int)k1.x, v0, acc1); acc1 = __dp4a((int)k1.y, v1, acc1);
            acc1 = __dp4a((int)k1.z, v2, acc1); acc1 = __dp4a((int)k1.w, v3, acc1);
            acc2 = __dp4a((int)k2.x, v0, acc2); acc2 = __dp4a((int)k2.y, v1, acc2);
            acc2 = __dp4a((int)k2.z, v2, acc2); acc2 = __dp4a((int)k2.w, v3, acc2);
            acc3 = __dp4a((int)k3.x, v0, acc3); acc3 = __dp4a((int)k3.y, v1, acc3);
            acc3 = __dp4a((int)k3.z, v2, acc3); acc3 = __dp4a((int)k3.w, v3, acc3);
        }
    }
    int* o = g_kvi + (size_t)tbh * (DH * DH);
    atomicAdd(&o[(d0 + 0) * 32 + e], acc0);
    atomicAdd(&o[(d0 + 1) * 32 + e], acc1);
    atomicAdd(&o[(d0 + 2) * 32 + e], acc2);
    atomicAdd(&o[(d0 + 3) * 32 + e], acc3);
}

// ---------------------------------------------------------------------------
// Kernel 3: o = quant((q_int . kv) * O_FACTOR) -> fp16 [tb][n][c].
// ---------------------------------------------------------------------------
__global__ void __launch_bounds__(256)
o_kernel() {
    int tbh = blockIdx.y;
    int tb = tbh >> 3, h = tbh & 7;
    __shared__ float kvs[DH * DH];
    for (int i = threadIdx.x; i < DH * DH; i += 256)
        kvs[i] = (float)g_kvi[(size_t)tbh * (DH * DH) + i] * (1.0f / 64.0f);
    __syncthreads();

    int n = (blockIdx.x * 256 + threadIdx.x) * 2;
    if (n >= NSP) return;

    const unsigned char* qp = g_q + ((size_t)(tb * C_) + h * DH) * NSP + n;
    float a0[32], a1[32];
#pragma unroll
    for (int e = 0; e < 32; e++) { a0[e] = 0.0f; a1[e] = 0.0f; }

#pragma unroll
    for (int d = 0; d < 32; d++) {
        uchar2 qd = *reinterpret_cast<const uchar2*>(qp + (size_t)d * NSP);
        float qx = (float)qd.x, qy = (float)qd.y;
        const float4* row = reinterpret_cast<const float4*>(&kvs[d * 32]);
#pragma unroll
        for (int e4 = 0; e4 < 8; e4++) {
            float4 kk = row[e4];
            a0[e4 * 4 + 0] += qx * kk.x;  a1[e4 * 4 + 0] += qy * kk.x;
            a0[e4 * 4 + 1] += qx * kk.y;  a1[e4 * 4 + 1] += qy * kk.y;
            a0[e4 * 4 + 2] += qx * kk.z;  a1[e4 * 4 + 2] += qy * kk.z;
            a0[e4 * 4 + 3] += qx * kk.w;  a1[e4 * 4 + 3] += qy * kk.w;
        }
    }

    __half* op0 = g_obf + ((size_t)tb * NSP + n) * C_ + h * DH;
#pragma unroll
    for (int half = 0; half < 2; half++) {
        float* a = half ? a1 : a0;
        uint32_t w[16];
#pragma unroll
        for (int e2 = 0; e2 < 16; e2++) {
            unsigned short lo = __half_as_ushort(__float2half_rn(quant8(a[e2 * 2 + 0] * O_FACTOR)));
            unsigned short hi = __half_as_ushort(__float2half_rn(quant8(a[e2 * 2 + 1] * O_FACTOR)));
            w[e2] = (uint32_t)lo | ((uint32_t)hi << 16);
        }
        __half* op = op0 + half * C_;
#pragma unroll
        for (int g = 0; g < 4; g++)
            reinterpret_cast<uint4*>(op)[g] = make_uint4(w[g * 4], w[g * 4 + 1], w[g * 4 + 2], w[g * 4 + 3]);
    }
}

// ---------------------------------------------------------------------------
extern "C" void kernel_launch(void* const* d_in, const int* in_sizes, int n_in,
                              void* d_out, int out_size) {
    const float* x   = (const float*)d_in[0];
    const float* qw  = (const float*)d_in[1];
    const float* qbn = (const float*)d_in[2];
    const float* kw  = (const float*)d_in[3];
    const float* kbn = (const float*)d_in[4];
    const float* vw  = (const float*)d_in[5];
    const float* vbn = (const float*)d_in[6];
    const float* pw  = (const float*)d_in[7];
    const float* pbn = (const float*)d_in[8];
    float* out = (float*)d_out;

    static int configured = 0;
    if (!configured) {
        cudaFuncSetAttribute(mma_gemm, cudaFuncAttributeMaxDynamicSharedMemorySize, 99328);
        configured = 1;
    }

    split_weights<<<1024, 256>>>(qw, kw, vw, pw);
    mma_gemm<<<dim3(25, 32), 256, 99328>>>(0, x, qbn, kbn, vbn, nullptr);
    kv_kernel<<<dim3(7, TB * HEADS), 256>>>();
    o_kernel<<<dim3(7, TB * HEADS), 256>>>();
    mma_gemm<<<dim3(25, 32), 256, 99328>>>(1, x, pbn, nullptr, nullptr, out);
}

// round 7
// speedup vs baseline: 1.0521x; 1.0521x over previous
#include <cuda_runtime.h>
#include <cuda_fp16.h>
#include <cstdint>
#include <cstddef>

#define TB    32
#define C_    256
#define NSP   3136
#define HEADS 8
#define DH    32
#define O_FACTOR 0.044194173824159216f

// ---------------- static scratch ----------------
__device__ unsigned char g_q[(size_t)TB * C_ * NSP];
__device__ unsigned char g_k[(size_t)TB * C_ * NSP];
__device__ unsigned char g_v[(size_t)TB * C_ * NSP];
__device__ __half g_xs[(size_t)TB * NSP * C_];    // [tb][n][c] quant(x)/8, fp16-exact
__device__ __half g_obf[(size_t)TB * NSP * C_];   // [tb][n][c] o ints 0..8
__device__ __half g_wA[2 * 768 * 256];            // qkv weights, 2-way fp16 split
__device__ __half g_wP[2 * 256 * 256];            // proj weights (x1/8), 2-way fp16 split
__device__ int g_kvi[TB * HEADS * DH * DH];       // exact integer kv accumulators

// ---------------- helpers ----------------
__device__ __forceinline__ float quant8(float x) {
    return fminf(fmaxf(rintf(x), 0.0f), 8.0f);
}
__device__ __forceinline__ uint32_t smem_u32(const void* p) {
    uint32_t a;
    asm("{ .reg .u64 t; cvta.to.shared.u64 t, %1; cvt.u32.u64 %0, t; }" : "=r"(a) : "l"(p));
    return a;
}
#define SWZ(x) ((x) ^ (((x) >> 3) & 0x70))

__device__ __forceinline__ void cp16(uint32_t s, const void* g, uint32_t nbytes) {
    asm volatile("cp.async.cg.shared.global [%0], [%1], 16, %2;"
                 :: "r"(s), "l"(g), "r"(nbytes) : "memory");
}
#define CP_COMMIT() asm volatile("cp.async.commit_group;" ::: "memory")
#define CP_WAIT1()  asm volatile("cp.async.wait_group 1;" ::: "memory")
#define CP_WAIT0()  asm volatile("cp.async.wait_group 0;" ::: "memory")

#define LDSM_X4(r0, r1, r2, r3, addr) \
    asm volatile("ldmatrix.sync.aligned.m8n8.x4.shared.b16 {%0,%1,%2,%3}, [%4];" \
                 : "=r"(r0), "=r"(r1), "=r"(r2), "=r"(r3) : "r"(addr))

#define MMA16816(c, a, b) \
    asm volatile("mma.sync.aligned.m16n8k16.row.col.f32.f16.f16.f32 " \
                 "{%0,%1,%2,%3}, {%4,%5,%6,%7}, {%8,%9}, {%0,%1,%2,%3};" \
                 : "+f"((c)[0]), "+f"((c)[1]), "+f"((c)[2]), "+f"((c)[3]) \
                 : "r"((a)[0]), "r"((a)[1]), "r"((a)[2]), "r"((a)[3]), \
                   "r"((b)[0]), "r"((b)[1]))

// ---------------------------------------------------------------------------
// Kernel 0: exact 2-way fp16 split of weights + zero the kv int accumulators.
// ---------------------------------------------------------------------------
__global__ void split_weights(const float* __restrict__ qw, const float* __restrict__ kw,
                              const float* __restrict__ vw, const float* __restrict__ pw) {
    int idx = blockIdx.x * 256 + threadIdx.x;  // 0..262143
    g_kvi[idx] = 0;                            // 262144 == TB*HEADS*DH*DH
    float w;
    __half* dst;
    int stride;
    if (idx < 196608) {
        int row = idx >> 8, col = idx & 255;
        w = (row < 256) ? qw[row * 256 + col]
          : (row < 512) ? kw[(row - 256) * 256 + col]
                        : vw[(row - 512) * 256 + col];
        dst = g_wA + idx; stride = 196608;
    } else {
        int i2 = idx - 196608;
        w = pw[i2] * 0.125f;
        dst = g_wP + i2; stride = 65536;
    }
    __half h1 = __float2half_rn(w);
    float f1 = __half2float(h1);
    __half h2 = __float2half_rn(w - f1);
    dst[0] = h1; dst[stride] = h2;
}

// ---------------------------------------------------------------------------
// Kernel 1: xs = quant(x)/8 -> fp16, transposed to [tb][n][c].
// ---------------------------------------------------------------------------
__global__ void __launch_bounds__(256)
transpose_x(const float* __restrict__ x) {
    __shared__ __half tile[32][34];
    int tb = blockIdx.z;
    int c0 = blockIdx.y << 5;
    int n0 = blockIdx.x << 5;
    int tid = threadIdx.x;
    int cc = tid >> 5, nn = tid & 31;
#pragma unroll
    for (int i = 0; i < 4; i++) {
        int c = c0 + cc + i * 8;
        float v = x[((size_t)(tb * C_) + c) * NSP + n0 + nn];
        tile[cc + i * 8][nn] = __float2half_rn(quant8(v) * 0.125f);
    }
    __syncthreads();
    int cl = tid & 31, r = tid >> 5;
#pragma unroll
    for (int i = 0; i < 4; i++) {
        int n = n0 + r + i * 8;
        g_xs[((size_t)tb * NSP + n) * C_ + c0 + cl] = tile[cl][r + i * 8];
    }
}

// ---------------------------------------------------------------------------
// Kernel 2: HMMA GEMM (R5 structure). B tile (128n x 256k) resident, A double
// buffered over 8 chunks. mode 0: qkv -> BN+quant -> SMEM-staged coalesced
// uint8 stores. mode 1: proj -> BN -> fp32 out.
// ---------------------------------------------------------------------------
__global__ void __launch_bounds__(256, 2)
mma_gemm(int mode, const float* __restrict__ bnA, const float* __restrict__ bnB,
         const float* __restrict__ bnC, float* __restrict__ outf) {
    extern __shared__ char smraw[];
    const uint32_t sbase = (smem_u32(smraw) + 1023u) & ~1023u;
    char* sm = smraw + (sbase - smem_u32(smraw));
    const uint32_t B_OFF = 0, A_OFF = 65536;   // B: 4 blocks x 16KB; A: 2 bufs x 16KB

    const int tid = threadIdx.x;
    const int lane = tid & 31;
    const int wid = tid >> 5;
    const int wm = wid >> 1;
    const int wn = wid & 1;
    const int n0 = blockIdx.x << 7;
    const int m0 = blockIdx.y << 7;
    const int tb = blockIdx.z;

    const __half* wsplit = mode ? g_wP : g_wA;
    const int wrows = mode ? 256 : 768;
    const __half* bsrc = (mode ? g_obf : g_xs) + (size_t)tb * NSP * C_;

    float acc[2][8][4];
#pragma unroll
    for (int i = 0; i < 2; i++)
#pragma unroll
        for (int j = 0; j < 8; j++)
#pragma unroll
            for (int l = 0; l < 4; l++) acc[i][j][l] = 0.0f;

    const int ks8 = tid & 7;
    const int rbase = tid >> 3;

    auto load_chunkA = [&](int c, int buf) {
        int s = c >> 2, kc = c & 3;
        const __half* abase = wsplit + ((size_t)s * wrows + m0) * 256 + kc * 64;
#pragma unroll
        for (int it = 0; it < 4; it++) {
            int row = it * 32 + rbase;
            uint32_t sa = sbase + A_OFF + buf * 16384 + SWZ(row * 128 + ks8 * 16);
            cp16(sa, abase + (size_t)row * 256 + ks8 * 8, 16);
        }
    };

    // B tile: full K=256 for 128 n rows, 4 kc-blocks of 16KB (resident)
#pragma unroll
    for (int it = 0; it < 16; it++) {
        int seg = it * 256 + tid;
        int blk = seg >> 10;
        int within = seg & 1023;
        int row = within >> 3;
        int k8 = within & 7;
        int gn = n0 + row;
        uint32_t ok = (gn < NSP) ? 16u : 0u;
        uint32_t sa = sbase + B_OFF + blk * 16384 + SWZ(row * 128 + k8 * 16);
        cp16(sa, bsrc + (size_t)gn * 256 + blk * 64 + k8 * 8, ok);
    }
    load_chunkA(0, 0);
    CP_COMMIT();
    load_chunkA(1, 1);
    CP_COMMIT();

#pragma unroll 1
    for (int c = 0; c < 8; c++) {
        if (c < 7) CP_WAIT1(); else CP_WAIT0();
        __syncthreads();

        uint32_t Ab = sbase + A_OFF + (c & 1) * 16384;
        uint32_t Bb = sbase + B_OFF + (c & 3) * 16384;
#pragma unroll
        for (int ks = 0; ks < 4; ks++) {
            uint32_t a[2][4], b[8][2];
#pragma unroll
            for (int tm = 0; tm < 2; tm++) {
                int row = wm * 32 + tm * 16 + (lane & 15);
                uint32_t ad = Ab + SWZ(row * 128 + ks * 32 + (lane >> 4) * 16);
                LDSM_X4(a[tm][0], a[tm][1], a[tm][2], a[tm][3], ad);
            }
#pragma unroll
            for (int tp = 0; tp < 4; tp++) {
                int row = wn * 64 + tp * 16 + (lane & 15);
                uint32_t bd = Bb + SWZ(row * 128 + ks * 32 + (lane >> 4) * 16);
                uint32_t r0, r1, r2, r3;
                LDSM_X4(r0, r1, r2, r3, bd);
                b[2 * tp][0] = r0; b[2 * tp][1] = r2;
                b[2 * tp + 1][0] = r1; b[2 * tp + 1][1] = r3;
            }
#pragma unroll
            for (int tm = 0; tm < 2; tm++)
#pragma unroll
                for (int tn = 0; tn < 8; tn++)
                    MMA16816(acc[tm][tn], a[tm], b[tn]);
        }
        __syncthreads();
        if (c + 2 <= 7) { load_chunkA(c + 2, (c + 2) & 1); CP_COMMIT(); }
    }

    // ---- epilogue ----
    if (mode == 0) {
        // BN + quant into SMEM staging (A buffers are drained), then coalesced stores.
        unsigned char* smout = reinterpret_cast<unsigned char*>(sm + A_OFF);
        __syncthreads();
#pragma unroll
        for (int tm = 0; tm < 2; tm++) {
#pragma unroll
            for (int h = 0; h < 2; h++) {
                int chr = wm * 32 + tm * 16 + (lane >> 2) + h * 8;   // 0..127
                int gm = m0 + chr;
                int mat = gm >> 8;
                const float* bn = (mat == 0) ? bnA : (mat == 1) ? bnB : bnC;
                int ch = gm & 255;
                float s_ = bn[ch] / sqrtf(bn[768 + ch] + 1e-5f);
                float t_ = __fsub_rn(bn[256 + ch], __fmul_rn(bn[512 + ch], s_));
#pragma unroll
                for (int tn = 0; tn < 8; tn++) {
                    int nr = wn * 64 + tn * 8 + (lane & 3) * 2;      // 0..127
                    float v0 = __fadd_rn(__fmul_rn(acc[tm][tn][2 * h + 0], s_), t_);
                    float v1 = __fadd_rn(__fmul_rn(acc[tm][tn][2 * h + 1], s_), t_);
                    smout[chr * 128 + nr]     = (unsigned char)quant8(v0);
                    smout[chr * 128 + nr + 1] = (unsigned char)quant8(v1);
                }
            }
        }
        __syncthreads();
        // coalesced store: 128 rows x 128 bytes = 1024 uint4
        int mat = m0 >> 8;  // whole 128-row tile is within one matrix (m0 mult of 128)
        unsigned char* out8 = (mat == 0) ? g_q : (mat == 1) ? g_k : g_v;
        int ch0 = m0 & 255;
#pragma unroll
        for (int p = 0; p < 4; p++) {
            int idx = p * 256 + tid;
            int row = idx >> 3, seg = idx & 7;
            int gn = n0 + seg * 16;
            if (gn < NSP) {
                uint4 val = *reinterpret_cast<const uint4*>(smout + row * 128 + seg * 16);
                *reinterpret_cast<uint4*>(out8 + ((size_t)(tb * C_) + ch0 + row) * NSP + gn) = val;
            }
        }
    } else {
#pragma unroll
        for (int tm = 0; tm < 2; tm++) {
#pragma unroll
            for (int h = 0; h < 2; h++) {
                int gm = m0 + wm * 32 + tm * 16 + (lane >> 2) + h * 8;
                float s_ = bnA[gm] / sqrtf(bnA[768 + gm] + 1e-5f);
                float t_ = __fsub_rn(bnA[256 + gm], __fmul_rn(bnA[512 + gm], s_));
                size_t base = ((size_t)(tb * C_) + gm) * NSP;
#pragma unroll
                for (int tn = 0; tn < 8; tn++) {
                    int n = n0 + wn * 64 + tn * 8 + (lane & 3) * 2;
                    if (n < NSP) {
                        float v0 = __fadd_rn(__fmul_rn(acc[tm][tn][2 * h + 0], s_), t_);
                        float v1 = __fadd_rn(__fmul_rn(acc[tm][tn][2 * h + 1], s_), t_);
                        *reinterpret_cast<float2*>(outf + base + n) = make_float2(v0, v1);
                    }
                }
            }
        }
    }
}

// ---------------------------------------------------------------------------
// Kernel 3: kv partial sums via dp4a over 64-n tiles (broadcast LDS for k,
// conflict-free LDS for v), atomicAdd(int) into g_kvi (exact).
// ---------------------------------------------------------------------------
__global__ void __launch_bounds__(256)
kv_kernel() {
    int tbh = blockIdx.y;
    int tb = tbh >> 3, h = tbh & 7;
    int nstart = blockIdx.x * 448;               // 7 chunks x 448 = 3136
    const unsigned char* kp = g_k + ((size_t)(tb * C_) + h * DH) * NSP + nstart;
    const unsigned char* vp = g_v + ((size_t)(tb * C_) + h * DH) * NSP + nstart;

    __shared__ uint32_t ks[32][20];
    __shared__ uint32_t vs[32][17];

    int tid = threadIdx.x;
    int fr = tid >> 3, fw = tid & 7;
    int vr = tid >> 4, vw = tid & 15;
    int d0 = (tid >> 5) * 4, e = tid & 31;
    int acc0 = 0, acc1 = 0, acc2 = 0, acc3 = 0;

#pragma unroll 1
    for (int it = 0; it < 7; it++) {
        int nn = it * 64;
        __syncthreads();
        uint2 kk = *reinterpret_cast<const uint2*>(kp + (size_t)fr * NSP + nn + fw * 8);
        ks[fr][fw * 2] = kk.x; ks[fr][fw * 2 + 1] = kk.y;
        vs[vr][vw]      = *reinterpret_cast<const uint32_t*>(vp + (size_t)vr * NSP + nn + vw * 4);
        vs[vr + 16][vw] = *reinterpret_cast<const uint32_t*>(vp + (size_t)(vr + 16) * NSP + nn + vw * 4);
        __syncthreads();
#pragma unroll
        for (int q = 0; q < 4; q++) {
            uint4 k0 = *reinterpret_cast<const uint4*>(&ks[d0 + 0][q * 4]);
            uint4 k1 = *reinterpret_cast<const uint4*>(&ks[d0 + 1][q * 4]);
            uint4 k2 = *reinterpret_cast<const uint4*>(&ks[d0 + 2][q * 4]);
            uint4 k3 = *reinterpret_cast<const uint4*>(&ks[d0 + 3][q * 4]);
            int v0 = (int)vs[e][q * 4 + 0];
            int v1 = (int)vs[e][q * 4 + 1];
            int v2 = (int)vs[e][q * 4 + 2];
            int v3 = (int)vs[e][q * 4 + 3];
            acc0 = __dp4a((int)k0.x, v0, acc0); acc0 = __dp4a((int)k0.y, v1, acc0);
            acc0 = __dp4a((int)k0.z, v2, acc0); acc0 = __dp4a((int)k0.w, v3, acc0);
            acc1 = __dp4a((int)k1.x, v0, acc1); acc1 = __dp4a((int)k1.y, v1, acc1);
            acc1 = __dp4a((int)k1.z, v2, acc1); acc1 = __dp4a((int)k1.w, v3, acc1);
            acc2 = __dp4a((int)k2.x, v0, acc2); acc2 = __dp4a((int)k2.y, v1, acc2);
            acc2 = __dp4a((int)k2.z, v2, acc2); acc2 = __dp4a((int)k2.w, v3, acc2);
            acc3 = __dp4a((int)k3.x, v0, acc3); acc3 = __dp4a((int)k3.y, v1, acc3);
            acc3 = __dp4a((int)k3.z, v2, acc3); acc3 = __dp4a((int)k3.w, v3, acc3);
        }
    }
    int* o = g_kvi + (size_t)tbh * (DH * DH);
    atomicAdd(&o[(d0 + 0) * 32 + e], acc0);
    atomicAdd(&o[(d0 + 1) * 32 + e], acc1);
    atomicAdd(&o[(d0 + 2) * 32 + e], acc2);
    atomicAdd(&o[(d0 + 3) * 32 + e], acc3);
}

// ---------------------------------------------------------------------------
// Kernel 4: o = quant((q . kv) * O_FACTOR) -> fp16 [tb][n][c].
// Cooperative SMEM q tile (coalesced loads); 1 position x 16 e per thread.
// ---------------------------------------------------------------------------
__global__ void __launch_bounds__(256)
o_kernel() {
    int tbh = blockIdx.y;
    int tb = tbh >> 3, h = tbh & 7;
    int n0 = blockIdx.x << 7;
    __shared__ float kvs[DH * DH];
    __shared__ uint32_t qs[32][33];
    int tid = threadIdx.x;

    for (int i = tid; i < DH * DH; i += 256)
        kvs[i] = (float)g_kvi[(size_t)tbh * (DH * DH) + i] * (1.0f / 64.0f);
    {
        int d = tid >> 3, seg = tid & 7;
        uint4 val = make_uint4(0, 0, 0, 0);
        int gn = n0 + seg * 16;
        if (gn < NSP)
            val = *reinterpret_cast<const uint4*>(
                g_q + ((size_t)(tb * C_) + h * DH + d) * NSP + gn);
        qs[d][seg * 4 + 0] = val.x; qs[d][seg * 4 + 1] = val.y;
        qs[d][seg * 4 + 2] = val.z; qs[d][seg * 4 + 3] = val.w;
    }
    __syncthreads();

    int n = tid & 127;
    int eh = tid >> 7;             // 0..1
    int gn = n0 + n;
    if (gn >= NSP) return;
    int e0 = eh * 16;
    int widx = n >> 2, sh = (n & 3) * 8;

    float acc[16];
#pragma unroll
    for (int e = 0; e < 16; e++) acc[e] = 0.0f;
#pragma unroll
    for (int d = 0; d < 32; d++) {
        float qd = (float)((qs[d][widx] >> sh) & 0xFFu);
        const float4* row = reinterpret_cast<const float4*>(&kvs[d * 32 + e0]);
#pragma unroll
        for (int e4 = 0; e4 < 4; e4++) {
            float4 kk = row[e4];
            acc[e4 * 4 + 0] += qd * kk.x;
            acc[e4 * 4 + 1] += qd * kk.y;
            acc[e4 * 4 + 2] += qd * kk.z;
            acc[e4 * 4 + 3] += qd * kk.w;
        }
    }

    uint32_t w[8];
#pragma unroll
    for (int e2 = 0; e2 < 8; e2++) {
        unsigned short lo = __half_as_ushort(__float2half_rn(quant8(acc[e2 * 2 + 0] * O_FACTOR)));
        unsigned short hi = __half_as_ushort(__float2half_rn(quant8(acc[e2 * 2 + 1] * O_FACTOR)));
        w[e2] = (uint32_t)lo | ((uint32_t)hi << 16);
    }
    __half* op = g_obf + ((size_t)tb * NSP + gn) * C_ + h * DH + e0;
    reinterpret_cast<uint4*>(op)[0] = make_uint4(w[0], w[1], w[2], w[3]);
    reinterpret_cast<uint4*>(op)[1] = make_uint4(w[4], w[5], w[6], w[7]);
}

// ---------------------------------------------------------------------------
extern "C" void kernel_launch(void* const* d_in, const int* in_sizes, int n_in,
                              void* d_out, int out_size) {
    const float* x   = (const float*)d_in[0];
    const float* qw  = (const float*)d_in[1];
    const float* qbn = (const float*)d_in[2];
    const float* kw  = (const float*)d_in[3];
    const float* kbn = (const float*)d_in[4];
    const float* vw  = (const float*)d_in[5];
    const float* vbn = (const float*)d_in[6];
    const float* pw  = (const float*)d_in[7];
    const float* pbn = (const float*)d_in[8];
    float* out = (float*)d_out;

    static int configured = 0;
    if (!configured) {
        cudaFuncSetAttribute(mma_gemm, cudaFuncAttributeMaxDynamicSharedMemorySize, 99328);
        configured = 1;
    }

    split_weights<<<1024, 256>>>(qw, kw, vw, pw);
    transpose_x<<<dim3(98, 8, TB), 256>>>(x);
    mma_gemm<<<dim3(25, 6, TB), 256, 99328>>>(0, qbn, kbn, vbn, nullptr);
    kv_kernel<<<dim3(7, TB * HEADS), 256>>>();
    o_kernel<<<dim3(25, TB * HEADS), 256>>>();
    mma_gemm<<<dim3(25, 2, TB), 256, 99328>>>(1, pbn, nullptr, nullptr, out);
}

// round 8
// speedup vs baseline: 1.1465x; 1.0897x over previous
#include <cuda_runtime.h>
#include <cuda_fp16.h>
#include <cstdint>
#include <cstddef>

#define TB    32
#define C_    256
#define NSP   3136
#define HEADS 8
#define DH    32
#define O_FACTOR 0.044194173824159216f

// ---------------- static scratch ----------------
__device__ unsigned char g_q[(size_t)TB * C_ * NSP];
__device__ unsigned char g_k[(size_t)TB * C_ * NSP];
__device__ unsigned char g_v[(size_t)TB * C_ * NSP];
__device__ __half g_xs[(size_t)TB * NSP * C_];    // [tb][n][c] quant(x)/8, fp16-exact
__device__ __half g_obf[(size_t)TB * NSP * C_];   // [tb][n][c] o ints 0..8
__device__ __half g_wA[2 * 768 * 256];            // qkv weights, 2-way fp16 split
__device__ __half g_wP[2 * 256 * 256];            // proj weights (x1/8), 2-way fp16 split
__device__ int g_kvi[TB * HEADS * DH * DH];       // exact integer kv accumulators

// ---------------- helpers ----------------
__device__ __forceinline__ float quant8(float x) {
    return fminf(fmaxf(rintf(x), 0.0f), 8.0f);
}
__device__ __forceinline__ uint32_t smem_u32(const void* p) {
    uint32_t a;
    asm("{ .reg .u64 t; cvta.to.shared.u64 t, %1; cvt.u32.u64 %0, t; }" : "=r"(a) : "l"(p));
    return a;
}
#define SWZ(x) ((x) ^ (((x) >> 3) & 0x70))

__device__ __forceinline__ void cp16(uint32_t s, const void* g, uint32_t nbytes) {
    asm volatile("cp.async.cg.shared.global [%0], [%1], 16, %2;"
                 :: "r"(s), "l"(g), "r"(nbytes) : "memory");
}
#define CP_COMMIT() asm volatile("cp.async.commit_group;" ::: "memory")
#define CP_WAIT1()  asm volatile("cp.async.wait_group 1;" ::: "memory")
#define CP_WAIT0()  asm volatile("cp.async.wait_group 0;" ::: "memory")

#define LDSM_X4(r0, r1, r2, r3, addr) \
    asm volatile("ldmatrix.sync.aligned.m8n8.x4.shared.b16 {%0,%1,%2,%3}, [%4];" \
                 : "=r"(r0), "=r"(r1), "=r"(r2), "=r"(r3) : "r"(addr))

#define MMA16816(c, a, b) \
    asm volatile("mma.sync.aligned.m16n8k16.row.col.f32.f16.f16.f32 " \
                 "{%0,%1,%2,%3}, {%4,%5,%6,%7}, {%8,%9}, {%0,%1,%2,%3};" \
                 : "+f"((c)[0]), "+f"((c)[1]), "+f"((c)[2]), "+f"((c)[3]) \
                 : "r"((a)[0]), "r"((a)[1]), "r"((a)[2]), "r"((a)[3]), \
                   "r"((b)[0]), "r"((b)[1]))

// ---------------------------------------------------------------------------
// Kernel 0: exact 2-way fp16 split of weights + zero the kv int accumulators.
// ---------------------------------------------------------------------------
__global__ void split_weights(const float* __restrict__ qw, const float* __restrict__ kw,
                              const float* __restrict__ vw, const float* __restrict__ pw) {
    int idx = blockIdx.x * 256 + threadIdx.x;  // 0..262143
    g_kvi[idx] = 0;                            // 262144 == TB*HEADS*DH*DH
    float w;
    __half* dst;
    int stride;
    if (idx < 196608) {
        int row = idx >> 8, col = idx & 255;
        w = (row < 256) ? qw[row * 256 + col]
          : (row < 512) ? kw[(row - 256) * 256 + col]
                        : vw[(row - 512) * 256 + col];
        dst = g_wA + idx; stride = 196608;
    } else {
        int i2 = idx - 196608;
        w = pw[i2] * 0.125f;
        dst = g_wP + i2; stride = 65536;
    }
    __half h1 = __float2half_rn(w);
    float f1 = __half2float(h1);
    __half h2 = __float2half_rn(w - f1);
    dst[0] = h1; dst[stride] = h2;
}

// ---------------------------------------------------------------------------
// Kernel 1: xs = quant(x)/8 -> fp16, transposed to [tb][n][c].
// ---------------------------------------------------------------------------
__global__ void __launch_bounds__(256)
transpose_x(const float* __restrict__ x) {
    __shared__ __half tile[32][34];
    int tb = blockIdx.z;
    int c0 = blockIdx.y << 5;
    int n0 = blockIdx.x << 5;
    int tid = threadIdx.x;
    int cc = tid >> 5, nn = tid & 31;
#pragma unroll
    for (int i = 0; i < 4; i++) {
        int c = c0 + cc + i * 8;
        float v = x[((size_t)(tb * C_) + c) * NSP + n0 + nn];
        tile[cc + i * 8][nn] = __float2half_rn(quant8(v) * 0.125f);
    }
    __syncthreads();
    int cl = tid & 31, r = tid >> 5;
#pragma unroll
    for (int i = 0; i < 4; i++) {
        int n = n0 + r + i * 8;
        g_xs[((size_t)tb * NSP + n) * C_ + c0 + cl] = tile[cl][r + i * 8];
    }
}

// ---------------------------------------------------------------------------
// Kernel 2: HMMA GEMM (R5 structure, direct-store epilogue). B tile resident,
// A double-buffered over 8 chunks (2 fp16 splits x 4).
// ---------------------------------------------------------------------------
__global__ void __launch_bounds__(256, 2)
mma_gemm(int mode, const float* __restrict__ bnA, const float* __restrict__ bnB,
         const float* __restrict__ bnC, float* __restrict__ outf) {
    extern __shared__ char smraw[];
    const uint32_t sbase = (smem_u32(smraw) + 1023u) & ~1023u;
    const uint32_t B_OFF = 0, A_OFF = 65536;

    const int tid = threadIdx.x;
    const int lane = tid & 31;
    const int wid = tid >> 5;
    const int wm = wid >> 1;
    const int wn = wid & 1;
    const int n0 = blockIdx.x << 7;
    const int m0 = blockIdx.y << 7;
    const int tb = blockIdx.z;

    const __half* wsplit = mode ? g_wP : g_wA;
    const int wrows = mode ? 256 : 768;
    const __half* bsrc = (mode ? g_obf : g_xs) + (size_t)tb * NSP * C_;

    float acc[2][8][4];
#pragma unroll
    for (int i = 0; i < 2; i++)
#pragma unroll
        for (int j = 0; j < 8; j++)
#pragma unroll
            for (int l = 0; l < 4; l++) acc[i][j][l] = 0.0f;

    const int ks8 = tid & 7;
    const int rbase = tid >> 3;

    auto load_chunkA = [&](int c, int buf) {
        int s = c >> 2, kc = c & 3;
        const __half* abase = wsplit + ((size_t)s * wrows + m0) * 256 + kc * 64;
#pragma unroll
        for (int it = 0; it < 4; it++) {
            int row = it * 32 + rbase;
            uint32_t sa = sbase + A_OFF + buf * 16384 + SWZ(row * 128 + ks8 * 16);
            cp16(sa, abase + (size_t)row * 256 + ks8 * 8, 16);
        }
    };

#pragma unroll
    for (int it = 0; it < 16; it++) {
        int seg = it * 256 + tid;
        int blk = seg >> 10;
        int within = seg & 1023;
        int row = within >> 3;
        int k8 = within & 7;
        int gn = n0 + row;
        uint32_t ok = (gn < NSP) ? 16u : 0u;
        uint32_t sa = sbase + B_OFF + blk * 16384 + SWZ(row * 128 + k8 * 16);
        cp16(sa, bsrc + (size_t)gn * 256 + blk * 64 + k8 * 8, ok);
    }
    load_chunkA(0, 0);
    CP_COMMIT();
    load_chunkA(1, 1);
    CP_COMMIT();

#pragma unroll 1
    for (int c = 0; c < 8; c++) {
        if (c < 7) CP_WAIT1(); else CP_WAIT0();
        __syncthreads();

        uint32_t Ab = sbase + A_OFF + (c & 1) * 16384;
        uint32_t Bb = sbase + B_OFF + (c & 3) * 16384;
#pragma unroll
        for (int ks = 0; ks < 4; ks++) {
            uint32_t a[2][4], b[8][2];
#pragma unroll
            for (int tm = 0; tm < 2; tm++) {
                int row = wm * 32 + tm * 16 + (lane & 15);
                uint32_t ad = Ab + SWZ(row * 128 + ks * 32 + (lane >> 4) * 16);
                LDSM_X4(a[tm][0], a[tm][1], a[tm][2], a[tm][3], ad);
            }
#pragma unroll
            for (int tp = 0; tp < 4; tp++) {
                int row = wn * 64 + tp * 16 + (lane & 15);
                uint32_t bd = Bb + SWZ(row * 128 + ks * 32 + (lane >> 4) * 16);
                uint32_t r0, r1, r2, r3;
                LDSM_X4(r0, r1, r2, r3, bd);
                b[2 * tp][0] = r0; b[2 * tp][1] = r2;
                b[2 * tp + 1][0] = r1; b[2 * tp + 1][1] = r3;
            }
#pragma unroll
            for (int tm = 0; tm < 2; tm++)
#pragma unroll
                for (int tn = 0; tn < 8; tn++)
                    MMA16816(acc[tm][tn], a[tm], b[tn]);
        }
        __syncthreads();
        if (c + 2 <= 7) { load_chunkA(c + 2, (c + 2) & 1); CP_COMMIT(); }
    }

    // ---- epilogue (direct stores, R5-style) ----
#pragma unroll
    for (int tm = 0; tm < 2; tm++) {
#pragma unroll
        for (int h = 0; h < 2; h++) {
            int gm = m0 + wm * 32 + tm * 16 + (lane >> 2) + h * 8;
            const float* bn;
            unsigned char* out8 = nullptr;
            int ch;
            if (mode == 0) {
                int mat = gm >> 8;
                bn = (mat == 0) ? bnA : (mat == 1) ? bnB : bnC;
                out8 = (mat == 0) ? g_q : (mat == 1) ? g_k : g_v;
                ch = gm & 255;
            } else {
                bn = bnA;
                ch = gm;
            }
            float s_ = bn[ch] / sqrtf(bn[768 + ch] + 1e-5f);
            float t_ = __fsub_rn(bn[256 + ch], __fmul_rn(bn[512 + ch], s_));
            size_t base = ((size_t)(tb * C_) + ch) * NSP;
#pragma unroll
            for (int tn = 0; tn < 8; tn++) {
                int n = n0 + wn * 64 + tn * 8 + (lane & 3) * 2;
                if (n < NSP) {
                    float v0 = __fadd_rn(__fmul_rn(acc[tm][tn][2 * h + 0], s_), t_);
                    float v1 = __fadd_rn(__fmul_rn(acc[tm][tn][2 * h + 1], s_), t_);
                    if (mode == 0) {
                        uchar2 u;
                        u.x = (unsigned char)quant8(v0);
                        u.y = (unsigned char)quant8(v1);
                        *reinterpret_cast<uchar2*>(out8 + base + n) = u;
                    } else {
                        *reinterpret_cast<float2*>(outf + base + n) = make_float2(v0, v1);
                    }
                }
            }
        }
    }
}

// ---------------------------------------------------------------------------
// Kernel 3: kv partial sums via dp4a over 64-n tiles (broadcast LDS for k,
// conflict-free LDS for v), atomicAdd(int) into g_kvi (exact).
// ---------------------------------------------------------------------------
__global__ void __launch_bounds__(256)
kv_kernel() {
    int tbh = blockIdx.y;
    int tb = tbh >> 3, h = tbh & 7;
    int nstart = blockIdx.x * 448;               // 7 chunks x 448 = 3136
    const unsigned char* kp = g_k + ((size_t)(tb * C_) + h * DH) * NSP + nstart;
    const unsigned char* vp = g_v + ((size_t)(tb * C_) + h * DH) * NSP + nstart;

    __shared__ uint32_t ks[32][20];
    __shared__ uint32_t vs[32][17];

    int tid = threadIdx.x;
    int fr = tid >> 3, fw = tid & 7;
    int vr = tid >> 4, vw = tid & 15;
    int d0 = (tid >> 5) * 4, e = tid & 31;
    int acc0 = 0, acc1 = 0, acc2 = 0, acc3 = 0;

#pragma unroll 1
    for (int it = 0; it < 7; it++) {
        int nn = it * 64;
        __syncthreads();
        uint2 kk = *reinterpret_cast<const uint2*>(kp + (size_t)fr * NSP + nn + fw * 8);
        ks[fr][fw * 2] = kk.x; ks[fr][fw * 2 + 1] = kk.y;
        vs[vr][vw]      = *reinterpret_cast<const uint32_t*>(vp + (size_t)vr * NSP + nn + vw * 4);
        vs[vr + 16][vw] = *reinterpret_cast<const uint32_t*>(vp + (size_t)(vr + 16) * NSP + nn + vw * 4);
        __syncthreads();
#pragma unroll
        for (int q = 0; q < 4; q++) {
            uint4 k0 = *reinterpret_cast<const uint4*>(&ks[d0 + 0][q * 4]);
            uint4 k1 = *reinterpret_cast<const uint4*>(&ks[d0 + 1][q * 4]);
            uint4 k2 = *reinterpret_cast<const uint4*>(&ks[d0 + 2][q * 4]);
            uint4 k3 = *reinterpret_cast<const uint4*>(&ks[d0 + 3][q * 4]);
            int v0 = (int)vs[e][q * 4 + 0];
            int v1 = (int)vs[e][q * 4 + 1];
            int v2 = (int)vs[e][q * 4 + 2];
            int v3 = (int)vs[e][q * 4 + 3];
            acc0 = __dp4a((int)k0.x, v0, acc0); acc0 = __dp4a((int)k0.y, v1, acc0);
            acc0 = __dp4a((int)k0.z, v2, acc0); acc0 = __dp4a((int)k0.w, v3, acc0);
            acc1 = __dp4a((int)k1.x, v0, acc1); acc1 = __dp4a((int)k1.y, v1, acc1);
            acc1 = __dp4a((int)k1.z, v2, acc1); acc1 = __dp4a((int)k1.w, v3, acc1);
            acc2 = __dp4a((int)k2.x, v0, acc2); acc2 = __dp4a((int)k2.y, v1, acc2);
            acc2 = __dp4a((int)k2.z, v2, acc2); acc2 = __dp4a((int)k2.w, v3, acc2);
            acc3 = __dp4a((int)k3.x, v0, acc3); acc3 = __dp4a((int)k3.y, v1, acc3);
            acc3 = __dp4a((int)k3.z, v2, acc3); acc3 = __dp4a((int)k3.w, v3, acc3);
        }
    }
    int* o = g_kvi + (size_t)tbh * (DH * DH);
    atomicAdd(&o[(d0 + 0) * 32 + e], acc0);
    atomicAdd(&o[(d0 + 1) * 32 + e], acc1);
    atomicAdd(&o[(d0 + 2) * 32 + e], acc2);
    atomicAdd(&o[(d0 + 3) * 32 + e], acc3);
}

// ---------------------------------------------------------------------------
// Kernel 4: o = quant((q . kv) * O_FACTOR) -> fp16 [tb][n][c].
// Cooperative SMEM q tile (coalesced loads); 1 position x 16 e per thread.
// ---------------------------------------------------------------------------
__global__ void __launch_bounds__(256)
o_kernel() {
    int tbh = blockIdx.y;
    int tb = tbh >> 3, h = tbh & 7;
    int n0 = blockIdx.x << 7;
    __shared__ float kvs[DH * DH];
    __shared__ uint32_t qs[32][33];
    int tid = threadIdx.x;

    for (int i = tid; i < DH * DH; i += 256)
        kvs[i] = (float)g_kvi[(size_t)tbh * (DH * DH) + i] * (1.0f / 64.0f);
    {
        int d = tid >> 3, seg = tid & 7;
        uint4 val = make_uint4(0, 0, 0, 0);
        int gn = n0 + seg * 16;
        if (gn < NSP)
            val = *reinterpret_cast<const uint4*>(
                g_q + ((size_t)(tb * C_) + h * DH + d) * NSP + gn);
        qs[d][seg * 4 + 0] = val.x; qs[d][seg * 4 + 1] = val.y;
        qs[d][seg * 4 + 2] = val.z; qs[d][seg * 4 + 3] = val.w;
    }
    __syncthreads();

    int n = tid & 127;
    int eh = tid >> 7;             // 0..1
    int gn = n0 + n;
    if (gn >= NSP) return;
    int e0 = eh * 16;
    int widx = n >> 2, sh = (n & 3) * 8;

    float acc[16];
#pragma unroll
    for (int e = 0; e < 16; e++) acc[e] = 0.0f;
#pragma unroll
    for (int d = 0; d < 32; d++) {
        float qd = (float)((qs[d][widx] >> sh) & 0xFFu);
        const float4* row = reinterpret_cast<const float4*>(&kvs[d * 32 + e0]);
#pragma unroll
        for (int e4 = 0; e4 < 4; e4++) {
            float4 kk = row[e4];
            acc[e4 * 4 + 0] += qd * kk.x;
            acc[e4 * 4 + 1] += qd * kk.y;
            acc[e4 * 4 + 2] += qd * kk.z;
            acc[e4 * 4 + 3] += qd * kk.w;
        }
    }

    uint32_t w[8];
#pragma unroll
    for (int e2 = 0; e2 < 8; e2++) {
        unsigned short lo = __half_as_ushort(__float2half_rn(quant8(acc[e2 * 2 + 0] * O_FACTOR)));
        unsigned short hi = __half_as_ushort(__float2half_rn(quant8(acc[e2 * 2 + 1] * O_FACTOR)));
        w[e2] = (uint32_t)lo | ((uint32_t)hi << 16);
    }
    __half* op = g_obf + ((size_t)tb * NSP + gn) * C_ + h * DH + e0;
    reinterpret_cast<uint4*>(op)[0] = make_uint4(w[0], w[1], w[2], w[3]);
    reinterpret_cast<uint4*>(op)[1] = make_uint4(w[4], w[5], w[6], w[7]);
}

// ---------------------------------------------------------------------------
extern "C" void kernel_launch(void* const* d_in, const int* in_sizes, int n_in,
                              void* d_out, int out_size) {
    const float* x   = (const float*)d_in[0];
    const float* qw  = (const float*)d_in[1];
    const float* qbn = (const float*)d_in[2];
    const float* kw  = (const float*)d_in[3];
    const float* kbn = (const float*)d_in[4];
    const float* vw  = (const float*)d_in[5];
    const float* vbn = (const float*)d_in[6];
    const float* pw  = (const float*)d_in[7];
    const float* pbn = (const float*)d_in[8];
    float* out = (float*)d_out;

    static int configured = 0;
    if (!configured) {
        cudaFuncSetAttribute(mma_gemm, cudaFuncAttributeMaxDynamicSharedMemorySize, 99328);
        configured = 1;
    }

    split_weights<<<1024, 256>>>(qw, kw, vw, pw);
    transpose_x<<<dim3(98, 8, TB), 256>>>(x);
    mma_gemm<<<dim3(25, 6, TB), 256, 99328>>>(0, qbn, kbn, vbn, nullptr);
    kv_kernel<<<dim3(7, TB * HEADS), 256>>>();
    o_kernel<<<dim3(25, TB * HEADS), 256>>>();
    mma_gemm<<<dim3(25, 2, TB), 256, 99328>>>(1, pbn, nullptr, nullptr, out);
}

// round 9
// speedup vs baseline: 1.1466x; 1.0001x over previous
#include <cuda_runtime.h>
#include <cuda_fp16.h>
#include <cstdint>
#include <cstddef>

#define TB    32
#define C_    256
#define NSP   3136
#define HEADS 8
#define DH    32
#define O_FACTOR 0.044194173824159216f

// ---------------- static scratch ----------------
__device__ unsigned char g_q[(size_t)TB * C_ * NSP];
__device__ unsigned char g_k[(size_t)TB * C_ * NSP];
__device__ unsigned char g_v[(size_t)TB * C_ * NSP];
__device__ __half g_xs[(size_t)TB * NSP * C_];    // [tb][n][c] quant(x)/8, fp16-exact
__device__ __half g_obf[(size_t)TB * NSP * C_];   // [tb][n][c] o ints 0..8
__device__ __half g_wA[2 * 768 * 256];            // qkv weights, 2-way fp16 split
__device__ __half g_wP[2 * 256 * 256];            // proj weights (x1/8), 2-way fp16 split
__device__ int g_kvi[TB * HEADS * DH * DH];       // exact integer kv accumulators

// ---------------- helpers ----------------
__device__ __forceinline__ float quant8(float x) {
    return fminf(fmaxf(rintf(x), 0.0f), 8.0f);
}
__device__ __forceinline__ uint32_t smem_u32(const void* p) {
    uint32_t a;
    asm("{ .reg .u64 t; cvta.to.shared.u64 t, %1; cvt.u32.u64 %0, t; }" : "=r"(a) : "l"(p));
    return a;
}
#define SWZ(x) ((x) ^ (((x) >> 3) & 0x70))

__device__ __forceinline__ void cp16(uint32_t s, const void* g, uint32_t nbytes) {
    asm volatile("cp.async.cg.shared.global [%0], [%1], 16, %2;"
                 :: "r"(s), "l"(g), "r"(nbytes) : "memory");
}
#define CP_COMMIT() asm volatile("cp.async.commit_group;" ::: "memory")
#define CP_WAIT1()  asm volatile("cp.async.wait_group 1;" ::: "memory")
#define CP_WAIT0()  asm volatile("cp.async.wait_group 0;" ::: "memory")

#define LDSM_X4(r0, r1, r2, r3, addr) \
    asm volatile("ldmatrix.sync.aligned.m8n8.x4.shared.b16 {%0,%1,%2,%3}, [%4];" \
                 : "=r"(r0), "=r"(r1), "=r"(r2), "=r"(r3) : "r"(addr))

#define MMA16816(c, a, b) \
    asm volatile("mma.sync.aligned.m16n8k16.row.col.f32.f16.f16.f32 " \
                 "{%0,%1,%2,%3}, {%4,%5,%6,%7}, {%8,%9}, {%0,%1,%2,%3};" \
                 : "+f"((c)[0]), "+f"((c)[1]), "+f"((c)[2]), "+f"((c)[3]) \
                 : "r"((a)[0]), "r"((a)[1]), "r"((a)[2]), "r"((a)[3]), \
                   "r"((b)[0]), "r"((b)[1]))

// ---------------------------------------------------------------------------
// Kernel 0: exact 2-way fp16 split of weights + zero the kv int accumulators.
// ---------------------------------------------------------------------------
__global__ void split_weights(const float* __restrict__ qw, const float* __restrict__ kw,
                              const float* __restrict__ vw, const float* __restrict__ pw) {
    int idx = blockIdx.x * 256 + threadIdx.x;  // 0..262143
    g_kvi[idx] = 0;                            // 262144 == TB*HEADS*DH*DH
    float w;
    __half* dst;
    int stride;
    if (idx < 196608) {
        int row = idx >> 8, col = idx & 255;
        w = (row < 256) ? qw[row * 256 + col]
          : (row < 512) ? kw[(row - 256) * 256 + col]
                        : vw[(row - 512) * 256 + col];
        dst = g_wA + idx; stride = 196608;
    } else {
        int i2 = idx - 196608;
        w = pw[i2] * 0.125f;
        dst = g_wP + i2; stride = 65536;
    }
    __half h1 = __float2half_rn(w);
    float f1 = __half2float(h1);
    __half h2 = __float2half_rn(w - f1);
    dst[0] = h1; dst[stride] = h2;
}

// ---------------------------------------------------------------------------
// Kernel 1: xs = quant(x)/8 -> fp16, transposed to [tb][n][c].
// ---------------------------------------------------------------------------
__global__ void __launch_bounds__(256)
transpose_x(const float* __restrict__ x) {
    __shared__ __half tile[32][34];
    int tb = blockIdx.z;
    int c0 = blockIdx.y << 5;
    int n0 = blockIdx.x << 5;
    int tid = threadIdx.x;
    int cc = tid >> 5, nn = tid & 31;
#pragma unroll
    for (int i = 0; i < 4; i++) {
        int c = c0 + cc + i * 8;
        float v = x[((size_t)(tb * C_) + c) * NSP + n0 + nn];
        tile[cc + i * 8][nn] = __float2half_rn(quant8(v) * 0.125f);
    }
    __syncthreads();
    int cl = tid & 31, r = tid >> 5;
#pragma unroll
    for (int i = 0; i < 4; i++) {
        int n = n0 + r + i * 8;
        g_xs[((size_t)tb * NSP + n) * C_ + c0 + cl] = tile[cl][r + i * 8];
    }
}

// ---------------------------------------------------------------------------
// Kernel 2: HMMA GEMM (R5 structure, direct-store epilogue). B tile resident,
// A double-buffered over 8 chunks (2 fp16 splits x 4).
// ---------------------------------------------------------------------------
__global__ void __launch_bounds__(256, 2)
mma_gemm(int mode, const float* __restrict__ bnA, const float* __restrict__ bnB,
         const float* __restrict__ bnC, float* __restrict__ outf) {
    extern __shared__ char smraw[];
    const uint32_t sbase = (smem_u32(smraw) + 1023u) & ~1023u;
    const uint32_t B_OFF = 0, A_OFF = 65536;

    const int tid = threadIdx.x;
    const int lane = tid & 31;
    const int wid = tid >> 5;
    const int wm = wid >> 1;
    const int wn = wid & 1;
    const int n0 = blockIdx.x << 7;
    const int m0 = blockIdx.y << 7;
    const int tb = blockIdx.z;

    const __half* wsplit = mode ? g_wP : g_wA;
    const int wrows = mode ? 256 : 768;
    const __half* bsrc = (mode ? g_obf : g_xs) + (size_t)tb * NSP * C_;

    float acc[2][8][4];
#pragma unroll
    for (int i = 0; i < 2; i++)
#pragma unroll
        for (int j = 0; j < 8; j++)
#pragma unroll
            for (int l = 0; l < 4; l++) acc[i][j][l] = 0.0f;

    const int ks8 = tid & 7;
    const int rbase = tid >> 3;

    auto load_chunkA = [&](int c, int buf) {
        int s = c >> 2, kc = c & 3;
        const __half* abase = wsplit + ((size_t)s * wrows + m0) * 256 + kc * 64;
#pragma unroll
        for (int it = 0; it < 4; it++) {
            int row = it * 32 + rbase;
            uint32_t sa = sbase + A_OFF + buf * 16384 + SWZ(row * 128 + ks8 * 16);
            cp16(sa, abase + (size_t)row * 256 + ks8 * 8, 16);
        }
    };

#pragma unroll
    for (int it = 0; it < 16; it++) {
        int seg = it * 256 + tid;
        int blk = seg >> 10;
        int within = seg & 1023;
        int row = within >> 3;
        int k8 = within & 7;
        int gn = n0 + row;
        uint32_t ok = (gn < NSP) ? 16u : 0u;
        uint32_t sa = sbase + B_OFF + blk * 16384 + SWZ(row * 128 + k8 * 16);
        cp16(sa, bsrc + (size_t)gn * 256 + blk * 64 + k8 * 8, ok);
    }
    load_chunkA(0, 0);
    CP_COMMIT();
    load_chunkA(1, 1);
    CP_COMMIT();

#pragma unroll 1
    for (int c = 0; c < 8; c++) {
        if (c < 7) CP_WAIT1(); else CP_WAIT0();
        __syncthreads();

        uint32_t Ab = sbase + A_OFF + (c & 1) * 16384;
        uint32_t Bb = sbase + B_OFF + (c & 3) * 16384;
#pragma unroll
        for (int ks = 0; ks < 4; ks++) {
            uint32_t a[2][4], b[8][2];
#pragma unroll
            for (int tm = 0; tm < 2; tm++) {
                int row = wm * 32 + tm * 16 + (lane & 15);
                uint32_t ad = Ab + SWZ(row * 128 + ks * 32 + (lane >> 4) * 16);
                LDSM_X4(a[tm][0], a[tm][1], a[tm][2], a[tm][3], ad);
            }
#pragma unroll
            for (int tp = 0; tp < 4; tp++) {
                int row = wn * 64 + tp * 16 + (lane & 15);
                uint32_t bd = Bb + SWZ(row * 128 + ks * 32 + (lane >> 4) * 16);
                uint32_t r0, r1, r2, r3;
                LDSM_X4(r0, r1, r2, r3, bd);
                b[2 * tp][0] = r0; b[2 * tp][1] = r2;
                b[2 * tp + 1][0] = r1; b[2 * tp + 1][1] = r3;
            }
#pragma unroll
            for (int tm = 0; tm < 2; tm++)
#pragma unroll
                for (int tn = 0; tn < 8; tn++)
                    MMA16816(acc[tm][tn], a[tm], b[tn]);
        }
        __syncthreads();
        if (c + 2 <= 7) { load_chunkA(c + 2, (c + 2) & 1); CP_COMMIT(); }
    }

    // ---- epilogue (direct stores, R5-style) ----
#pragma unroll
    for (int tm = 0; tm < 2; tm++) {
#pragma unroll
        for (int h = 0; h < 2; h++) {
            int gm = m0 + wm * 32 + tm * 16 + (lane >> 2) + h * 8;
            const float* bn;
            unsigned char* out8 = nullptr;
            int ch;
            if (mode == 0) {
                int mat = gm >> 8;
                bn = (mat == 0) ? bnA : (mat == 1) ? bnB : bnC;
                out8 = (mat == 0) ? g_q : (mat == 1) ? g_k : g_v;
                ch = gm & 255;
            } else {
                bn = bnA;
                ch = gm;
            }
            float s_ = bn[ch] / sqrtf(bn[768 + ch] + 1e-5f);
            float t_ = __fsub_rn(bn[256 + ch], __fmul_rn(bn[512 + ch], s_));
            size_t base = ((size_t)(tb * C_) + ch) * NSP;
#pragma unroll
            for (int tn = 0; tn < 8; tn++) {
                int n = n0 + wn * 64 + tn * 8 + (lane & 3) * 2;
                if (n < NSP) {
                    float v0 = __fadd_rn(__fmul_rn(acc[tm][tn][2 * h + 0], s_), t_);
                    float v1 = __fadd_rn(__fmul_rn(acc[tm][tn][2 * h + 1], s_), t_);
                    if (mode == 0) {
                        uchar2 u;
                        u.x = (unsigned char)quant8(v0);
                        u.y = (unsigned char)quant8(v1);
                        *reinterpret_cast<uchar2*>(out8 + base + n) = u;
                    } else {
                        *reinterpret_cast<float2*>(outf + base + n) = make_float2(v0, v1);
                    }
                }
            }
        }
    }
}

// ---------------------------------------------------------------------------
// Kernel 3: kv partial sums via dp4a over 64-n tiles (broadcast LDS for k,
// conflict-free LDS for v), atomicAdd(int) into g_kvi (exact).
// ---------------------------------------------------------------------------
__global__ void __launch_bounds__(256)
kv_kernel() {
    int tbh = blockIdx.y;
    int tb = tbh >> 3, h = tbh & 7;
    int nstart = blockIdx.x * 448;               // 7 chunks x 448 = 3136
    const unsigned char* kp = g_k + ((size_t)(tb * C_) + h * DH) * NSP + nstart;
    const unsigned char* vp = g_v + ((size_t)(tb * C_) + h * DH) * NSP + nstart;

    __shared__ uint32_t ks[32][20];
    __shared__ uint32_t vs[32][17];

    int tid = threadIdx.x;
    int fr = tid >> 3, fw = tid & 7;
    int vr = tid >> 4, vw = tid & 15;
    int d0 = (tid >> 5) * 4, e = tid & 31;
    int acc0 = 0, acc1 = 0, acc2 = 0, acc3 = 0;

#pragma unroll 1
    for (int it = 0; it < 7; it++) {
        int nn = it * 64;
        __syncthreads();
        uint2 kk = *reinterpret_cast<const uint2*>(kp + (size_t)fr * NSP + nn + fw * 8);
        ks[fr][fw * 2] = kk.x; ks[fr][fw * 2 + 1] = kk.y;
        vs[vr][vw]      = *reinterpret_cast<const uint32_t*>(vp + (size_t)vr * NSP + nn + vw * 4);
        vs[vr + 16][vw] = *reinterpret_cast<const uint32_t*>(vp + (size_t)(vr + 16) * NSP + nn + vw * 4);
        __syncthreads();
#pragma unroll
        for (int q = 0; q < 4; q++) {
            uint4 k0 = *reinterpret_cast<const uint4*>(&ks[d0 + 0][q * 4]);
            uint4 k1 = *reinterpret_cast<const uint4*>(&ks[d0 + 1][q * 4]);
            uint4 k2 = *reinterpret_cast<const uint4*>(&ks[d0 + 2][q * 4]);
            uint4 k3 = *reinterpret_cast<const uint4*>(&ks[d0 + 3][q * 4]);
            int v0 = (int)vs[e][q * 4 + 0];
            int v1 = (int)vs[e][q * 4 + 1];
            int v2 = (int)vs[e][q * 4 + 2];
            int v3 = (int)vs[e][q * 4 + 3];
            acc0 = __dp4a((int)k0.x, v0, acc0); acc0 = __dp4a((int)k0.y, v1, acc0);
            acc0 = __dp4a((int)k0.z, v2, acc0); acc0 = __dp4a((int)k0.w, v3, acc0);
            acc1 = __dp4a((int)k1.x, v0, acc1); acc1 = __dp4a((int)k1.y, v1, acc1);
            acc1 = __dp4a((int)k1.z, v2, acc1); acc1 = __dp4a((int)k1.w, v3, acc1);
            acc2 = __dp4a((int)k2.x, v0, acc2); acc2 = __dp4a((int)k2.y, v1, acc2);
            acc2 = __dp4a((int)k2.z, v2, acc2); acc2 = __dp4a((int)k2.w, v3, acc2);
            acc3 = __dp4a((int)k3.x, v0, acc3); acc3 = __dp4a((int)k3.y, v1, acc3);
            acc3 = __dp4a((int)k3.z, v2, acc3); acc3 = __dp4a((int)k3.w, v3, acc3);
        }
    }
    int* o = g_kvi + (size_t)tbh * (DH * DH);
    atomicAdd(&o[(d0 + 0) * 32 + e], acc0);
    atomicAdd(&o[(d0 + 1) * 32 + e], acc1);
    atomicAdd(&o[(d0 + 2) * 32 + e], acc2);
    atomicAdd(&o[(d0 + 3) * 32 + e], acc3);
}

// ---------------------------------------------------------------------------
// Kernel 4: o = quant((q . kv) * O_FACTOR) -> fp16 [tb][n][c].
// Cooperative SMEM q tile (coalesced loads); 1 position x 16 e per thread.
// ---------------------------------------------------------------------------
__global__ void __launch_bounds__(256)
o_kernel() {
    int tbh = blockIdx.y;
    int tb = tbh >> 3, h = tbh & 7;
    int n0 = blockIdx.x << 7;
    __shared__ float kvs[DH * DH];
    __shared__ uint32_t qs[32][33];
    int tid = threadIdx.x;

    for (int i = tid; i < DH * DH; i += 256)
        kvs[i] = (float)g_kvi[(size_t)tbh * (DH * DH) + i] * (1.0f / 64.0f);
    {
        int d = tid >> 3, seg = tid & 7;
        uint4 val = make_uint4(0, 0, 0, 0);
        int gn = n0 + seg * 16;
        if (gn < NSP)
            val = *reinterpret_cast<const uint4*>(
                g_q + ((size_t)(tb * C_) + h * DH + d) * NSP + gn);
        qs[d][seg * 4 + 0] = val.x; qs[d][seg * 4 + 1] = val.y;
        qs[d][seg * 4 + 2] = val.z; qs[d][seg * 4 + 3] = val.w;
    }
    __syncthreads();

    int n = tid & 127;
    int eh = tid >> 7;             // 0..1
    int gn = n0 + n;
    if (gn >= NSP) return;
    int e0 = eh * 16;
    int widx = n >> 2, sh = (n & 3) * 8;

    float acc[16];
#pragma unroll
    for (int e = 0; e < 16; e++) acc[e] = 0.0f;
#pragma unroll
    for (int d = 0; d < 32; d++) {
        float qd = (float)((qs[d][widx] >> sh) & 0xFFu);
        const float4* row = reinterpret_cast<const float4*>(&kvs[d * 32 + e0]);
#pragma unroll
        for (int e4 = 0; e4 < 4; e4++) {
            float4 kk = row[e4];
            acc[e4 * 4 + 0] += qd * kk.x;
            acc[e4 * 4 + 1] += qd * kk.y;
            acc[e4 * 4 + 2] += qd * kk.z;
            acc[e4 * 4 + 3] += qd * kk.w;
        }
    }

    uint32_t w[8];
#pragma unroll
    for (int e2 = 0; e2 < 8; e2++) {
        unsigned short lo = __half_as_ushort(__float2half_rn(quant8(acc[e2 * 2 + 0] * O_FACTOR)));
        unsigned short hi = __half_as_ushort(__float2half_rn(quant8(acc[e2 * 2 + 1] * O_FACTOR)));
        w[e2] = (uint32_t)lo | ((uint32_t)hi << 16);
    }
    __half* op = g_obf + ((size_t)tb * NSP + gn) * C_ + h * DH + e0;
    reinterpret_cast<uint4*>(op)[0] = make_uint4(w[0], w[1], w[2], w[3]);
    reinterpret_cast<uint4*>(op)[1] = make_uint4(w[4], w[5], w[6], w[7]);
}

// ---------------------------------------------------------------------------
extern "C" void kernel_launch(void* const* d_in, const int* in_sizes, int n_in,
                              void* d_out, int out_size) {
    const float* x   = (const float*)d_in[0];
    const float* qw  = (const float*)d_in[1];
    const float* qbn = (const float*)d_in[2];
    const float* kw  = (const float*)d_in[3];
    const float* kbn = (const float*)d_in[4];
    const float* vw  = (const float*)d_in[5];
    const float* vbn = (const float*)d_in[6];
    const float* pw  = (const float*)d_in[7];
    const float* pbn = (const float*)d_in[8];
    float* out = (float*)d_out;

    static int configured = 0;
    if (!configured) {
        cudaFuncSetAttribute(mma_gemm, cudaFuncAttributeMaxDynamicSharedMemorySize, 99328);
        configured = 1;
    }

    split_weights<<<1024, 256>>>(qw, kw, vw, pw);
    transpose_x<<<dim3(98, 8, TB), 256>>>(x);
    mma_gemm<<<dim3(25, 6, TB), 256, 99328>>>(0, qbn, kbn, vbn, nullptr);
    kv_kernel<<<dim3(7, TB * HEADS), 256>>>();
    o_kernel<<<dim3(25, TB * HEADS), 256>>>();
    mma_gemm<<<dim3(25, 2, TB), 256, 99328>>>(1, pbn, nullptr, nullptr, out);
}